// round 14
// baseline (speedup 1.0000x reference)
#include <cuda_runtime.h>
#include <cstdint>

#define H_DIM   4096
#define R_DIM   16
#define N_TOK   32768          // B*S
#define TB2     16             // tokens per block (kernel2, R9-proven)
#define NTHREADS 256
#define KSCALE ((float)(2.0 / 0.95))
#define PDROP  0.05f

// kernel1: 16 tokens/block, H in 32 chunks of 128 floats, 512 threads
#define K1_TB   16
#define K1_C    128
#define K1_NCH  (H_DIM / K1_C)   // 32
#define K1_THR  512

__device__ float g_mid[N_TOK * R_DIM];        // 2 MB scratch
__device__ float g_bt[8 * R_DIM * H_DIM];     // 2 MB: Bt[e][r][h]

// ---------------------------------------------------------------------------
// Kernel 0: transpose lora_b[e][h][r] -> g_bt[e][r][h]  (~6us)
// ---------------------------------------------------------------------------
__global__ void transpose_b_kernel(const float* __restrict__ lora_b)
{
    const int idx = blockIdx.x * blockDim.x + threadIdx.x;   // 524288
    const int r = idx & 15;
    const int h = (idx >> 4) & 4095;
    const int e = idx >> 16;
    g_bt[((size_t)e * R_DIM + r) * H_DIM + h] = lora_b[idx];
}

// ---------------------------------------------------------------------------
// Kernel 1: mid[g][r] = sum_h dropped(g,h) * A[e][r][h]
// 512 threads/block (16 warps), 16 tokens/block. Warp w -> token-group
// tg=w>>2 (4 tokens) x r-group rg=w&3 (4 r's). acc[4][4]=16 regs; total
// ~55 regs under launch_bounds(512,2) -> 32 warps/SM = 50% occ (2x R13).
// Double-buffered smem staging, TWO barriers/chunk (phase-separated, R12
// lesson), unroll 1 (R13 lesson). Each thread stages ONE float4 per chunk.
// ---------------------------------------------------------------------------
__global__ __launch_bounds__(K1_THR, 2)
void lora_mid_kernel(const float* __restrict__ data,
                     const float* __restrict__ mask,
                     const float* __restrict__ lora_a)
{
    const int tid  = threadIdx.x;
    const int wid  = tid >> 5;           // 0..15
    const int lane = tid & 31;
    const int tg   = wid >> 2;           // 0..3 : tokens [4*tg, 4*tg+4)
    const int rg   = wid & 3;            // 0..3 : r in [4*rg, 4*rg+4)
    const int g0   = blockIdx.x * K1_TB;
    const int e    = blockIdx.x >> 8;    // 256 blocks per expert
    const float* aBase = lora_a + ((size_t)e * R_DIM + 4 * rg) * H_DIM;

    // staging: thread -> (token stok, float4-slot sf); warp-coalesced
    const int stok = tid >> 5;           // 0..15 (== wid)
    const int sf   = tid & 31;           // 0..31
    const size_t sbase = (size_t)(g0 + stok) * H_DIM;

    __shared__ float4 sbuf[2][K1_TB][K1_C / 4];   // 16KB

    float acc[4][4];
#pragma unroll
    for (int t = 0; t < 4; t++)
#pragma unroll
        for (int j = 0; j < 4; j++) acc[t][j] = 0.f;

    // prefetch chunk 0 (one float4 of data + mask per thread)
    float4 dx, mx;
    dx = __ldcs((const float4*)(data + sbase + sf * 4));
    mx = __ldcs((const float4*)(mask + sbase + sf * 4));

#pragma unroll 1
    for (int ch = 0; ch < K1_NCH; ch++) {
        const int buf = ch & 1;

        // dropout + stage to smem
        float4 d;
        d.x = (mx.x >= PDROP) ? dx.x * KSCALE : 0.f;
        d.y = (mx.y >= PDROP) ? dx.y * KSCALE : 0.f;
        d.z = (mx.z >= PDROP) ? dx.z * KSCALE : 0.f;
        d.w = (mx.w >= PDROP) ? dx.w * KSCALE : 0.f;
        sbuf[buf][stok][sf] = d;

        // prefetch next chunk (chunk 31 reloads itself harmlessly)
        {
            const int nch = (ch + 1 < K1_NCH) ? ch + 1 : ch;
            const size_t base = sbase + (size_t)nch * K1_C;
            dx = __ldcs((const float4*)(data + base + sf * 4));
            mx = __ldcs((const float4*)(mask + base + sf * 4));
        }

        __syncthreads();

        // this warp's 4 A rows for this chunk (L1-dedup across the 4 warps
        // sharing rg)
        const int hoff = ch * K1_C + lane * 4;
        const float4 a0 = *(const float4*)(aBase + 0 * H_DIM + hoff);
        const float4 a1 = *(const float4*)(aBase + 1 * H_DIM + hoff);
        const float4 a2 = *(const float4*)(aBase + 2 * H_DIM + hoff);
        const float4 a3 = *(const float4*)(aBase + 3 * H_DIM + hoff);

        // accumulate this warp's 4 tokens x 4 r
#pragma unroll
        for (int t = 0; t < 4; t++) {
            const float4 v = sbuf[buf][4 * tg + t][lane];
            acc[t][0] += v.x * a0.x + v.y * a0.y + v.z * a0.z + v.w * a0.w;
            acc[t][1] += v.x * a1.x + v.y * a1.y + v.z * a1.z + v.w * a1.w;
            acc[t][2] += v.x * a2.x + v.y * a2.y + v.z * a2.z + v.w * a2.w;
            acc[t][3] += v.x * a3.x + v.y * a3.y + v.z * a3.z + v.w * a3.w;
        }

        __syncthreads();
    }

    // reduce over lanes (h) and store
#pragma unroll
    for (int t = 0; t < 4; t++) {
#pragma unroll
        for (int j = 0; j < 4; j++) {
            float s = acc[t][j];
#pragma unroll
            for (int off = 16; off > 0; off >>= 1)
                s += __shfl_xor_sync(0xffffffffu, s, off);
            if (lane == 0)
                g_mid[(size_t)(g0 + 4 * tg + t) * R_DIM + 4 * rg + j] = s;
        }
    }
}

// ---------------------------------------------------------------------------
// Kernel 2: out[g][h] = result[g][h] + sum_r mid[g][r] * Bt[e][r][h]
// R11-exact champion. TB2=16, two batches of 8 tokens.
// ---------------------------------------------------------------------------
__global__ __launch_bounds__(NTHREADS)
void lora_out_kernel(const float* __restrict__ result,
                     float* __restrict__ out)
{
    const int tid = threadIdx.x;
    const int g0  = blockIdx.x * TB2;
    const int e   = g0 >> 12;
    const int h4  = (blockIdx.y * NTHREADS + tid) * 4;
    const float* btBase = g_bt + (size_t)e * (R_DIM * H_DIM);

    __shared__ float smid[TB2 * R_DIM];
    smid[tid] = g_mid[(size_t)g0 * R_DIM + tid];
    __syncthreads();

    float4 acc[TB2];
#pragma unroll
    for (int t = 0; t < 8; t++)
        acc[t] = __ldcs((const float4*)(result + (size_t)(g0 + t) * H_DIM + h4));

#pragma unroll
    for (int r = 0; r < R_DIM; r++) {
        const float4 b4 = *(const float4*)(btBase + (size_t)r * H_DIM + h4);
#pragma unroll
        for (int t = 0; t < 8; t++) {
            const float m = smid[t * R_DIM + r];
            acc[t].x += m * b4.x;
            acc[t].y += m * b4.y;
            acc[t].z += m * b4.z;
            acc[t].w += m * b4.w;
        }
    }
#pragma unroll
    for (int t = 0; t < 8; t++)
        __stcs((float4*)(out + (size_t)(g0 + t) * H_DIM + h4), acc[t]);

#pragma unroll
    for (int t = 8; t < TB2; t++)
        acc[t] = __ldcs((const float4*)(result + (size_t)(g0 + t) * H_DIM + h4));

#pragma unroll
    for (int r = 0; r < R_DIM; r++) {
        const float4 b4 = *(const float4*)(btBase + (size_t)r * H_DIM + h4);
#pragma unroll
        for (int t = 8; t < TB2; t++) {
            const float m = smid[t * R_DIM + r];
            acc[t].x += m * b4.x;
            acc[t].y += m * b4.y;
            acc[t].z += m * b4.z;
            acc[t].w += m * b4.w;
        }
    }
#pragma unroll
    for (int t = 8; t < TB2; t++)
        __stcs((float4*)(out + (size_t)(g0 + t) * H_DIM + h4), acc[t]);
}

// ---------------------------------------------------------------------------
// Launch order: mid FIRST (ncu -s5 -c1 profiles lora_mid), then transpose,
// then out. Dependencies respected.
// ---------------------------------------------------------------------------
extern "C" void kernel_launch(void* const* d_in, const int* in_sizes, int n_in,
                              void* d_out, int out_size)
{
    const float* result   = (const float*)d_in[0];
    const float* data     = (const float*)d_in[1];
    const float* dropmask = (const float*)d_in[2];
    const float* lora_a   = (const float*)d_in[3];
    const float* lora_b   = (const float*)d_in[4];
    float* out = (float*)d_out;

    lora_mid_kernel<<<N_TOK / K1_TB, K1_THR>>>(data, dropmask, lora_a);
    transpose_b_kernel<<<(8 * R_DIM * H_DIM) / NTHREADS, NTHREADS>>>(lora_b);

    dim3 grid2(N_TOK / TB2, H_DIM / (4 * NTHREADS));
    lora_out_kernel<<<grid2, NTHREADS>>>(result, out);
}

// round 15
// speedup vs baseline: 1.5413x; 1.5413x over previous
#include <cuda_runtime.h>
#include <cstdint>

#define H_DIM   4096
#define R_DIM   16
#define N_TOK   32768          // B*S
#define TB2     16             // tokens per block (kernel2, R9-proven)
#define NTHREADS 256
#define KSCALE ((float)(2.0 / 0.95))
#define PDROP  0.05f

// kernel1: 16 tokens/block, H in 32 chunks of 128 floats
#define K1_TB   16
#define K1_C    128
#define K1_NCH  (H_DIM / K1_C)   // 32

__device__ float g_mid[N_TOK * R_DIM];        // 2 MB scratch
__device__ float g_bt[8 * R_DIM * H_DIM];     // 2 MB: Bt[e][r][h]

// ---------------------------------------------------------------------------
// Kernel 0: transpose lora_b[e][h][r] -> g_bt[e][r][h]  (~6us)
// ---------------------------------------------------------------------------
__global__ void transpose_b_kernel(const float* __restrict__ lora_b)
{
    const int idx = blockIdx.x * blockDim.x + threadIdx.x;   // 524288
    const int r = idx & 15;
    const int h = (idx >> 4) & 4095;
    const int e = idx >> 16;
    g_bt[((size_t)e * R_DIM + r) * H_DIM + h] = lora_b[idx];
}

// ---------------------------------------------------------------------------
// Kernel 1: mid[g][r] = sum_h dropped(g,h) * A[e][r][h]
// R11-champion shape: 256 threads, 16 tokens/block; warp w -> 8 tokens
// (tg=w>>2) x 4 r's (rg=w&3); double-buffered smem staging, TWO barriers
// per chunk, unroll 1. ONLY change vs champion: __launch_bounds__(256,3)
// -> 3 blocks/SM (36% occ, +50% warps) at unchanged wavefront count.
// ---------------------------------------------------------------------------
__global__ __launch_bounds__(NTHREADS, 3)
void lora_mid_kernel(const float* __restrict__ data,
                     const float* __restrict__ mask,
                     const float* __restrict__ lora_a)
{
    const int tid  = threadIdx.x;
    const int wid  = tid >> 5;           // 0..7
    const int lane = tid & 31;
    const int tg   = wid >> 2;           // 0..1 : tokens [8*tg, 8*tg+8)
    const int rg   = wid & 3;            // 0..3 : r in [4*rg, 4*rg+4)
    const int g0   = blockIdx.x * K1_TB;
    const int e    = blockIdx.x >> 8;    // 256 blocks per expert
    const float* aBase = lora_a + ((size_t)e * R_DIM + 4 * rg) * H_DIM;

    // staging assignment: thread -> (token stok, float4-slots sf and sf+16)
    const int stok = tid >> 4;           // 0..15
    const int sf   = tid & 15;           // 0..15
    const size_t sbase = (size_t)(g0 + stok) * H_DIM;

    __shared__ float4 sbuf[2][K1_TB][K1_C / 4];   // 16KB

    float acc[8][4];
#pragma unroll
    for (int t = 0; t < 8; t++)
#pragma unroll
        for (int j = 0; j < 4; j++) acc[t][j] = 0.f;

    // prefetch chunk 0
    float4 dx0, dx1, mx0, mx1;
    {
        dx0 = __ldcs((const float4*)(data + sbase + sf * 4));
        dx1 = __ldcs((const float4*)(data + sbase + (sf + 16) * 4));
        mx0 = __ldcs((const float4*)(mask + sbase + sf * 4));
        mx1 = __ldcs((const float4*)(mask + sbase + (sf + 16) * 4));
    }

#pragma unroll 1
    for (int ch = 0; ch < K1_NCH; ch++) {
        const int buf = ch & 1;

        // dropout + stage to smem
        float4 d0, d1;
        d0.x = (mx0.x >= PDROP) ? dx0.x * KSCALE : 0.f;
        d0.y = (mx0.y >= PDROP) ? dx0.y * KSCALE : 0.f;
        d0.z = (mx0.z >= PDROP) ? dx0.z * KSCALE : 0.f;
        d0.w = (mx0.w >= PDROP) ? dx0.w * KSCALE : 0.f;
        d1.x = (mx1.x >= PDROP) ? dx1.x * KSCALE : 0.f;
        d1.y = (mx1.y >= PDROP) ? dx1.y * KSCALE : 0.f;
        d1.z = (mx1.z >= PDROP) ? dx1.z * KSCALE : 0.f;
        d1.w = (mx1.w >= PDROP) ? dx1.w * KSCALE : 0.f;
        sbuf[buf][stok][sf]      = d0;
        sbuf[buf][stok][sf + 16] = d1;

        // prefetch next chunk (chunk 31 reloads itself harmlessly)
        {
            const int nch = (ch + 1 < K1_NCH) ? ch + 1 : ch;
            const size_t base = sbase + (size_t)nch * K1_C;
            dx0 = __ldcs((const float4*)(data + base + sf * 4));
            dx1 = __ldcs((const float4*)(data + base + (sf + 16) * 4));
            mx0 = __ldcs((const float4*)(mask + base + sf * 4));
            mx1 = __ldcs((const float4*)(mask + base + (sf + 16) * 4));
        }

        __syncthreads();

        // this warp's 4 A rows for this chunk (gmem; L1-shared across warps)
        const int hoff = ch * K1_C + lane * 4;
        const float4 a0 = *(const float4*)(aBase + 0 * H_DIM + hoff);
        const float4 a1 = *(const float4*)(aBase + 1 * H_DIM + hoff);
        const float4 a2 = *(const float4*)(aBase + 2 * H_DIM + hoff);
        const float4 a3 = *(const float4*)(aBase + 3 * H_DIM + hoff);

        // accumulate this warp's 8 tokens x 4 r
#pragma unroll
        for (int t = 0; t < 8; t++) {
            const float4 v = sbuf[buf][8 * tg + t][lane];
            acc[t][0] += v.x * a0.x + v.y * a0.y + v.z * a0.z + v.w * a0.w;
            acc[t][1] += v.x * a1.x + v.y * a1.y + v.z * a1.z + v.w * a1.w;
            acc[t][2] += v.x * a2.x + v.y * a2.y + v.z * a2.z + v.w * a2.w;
            acc[t][3] += v.x * a3.x + v.y * a3.y + v.z * a3.z + v.w * a3.w;
        }

        __syncthreads();
    }

    // reduce over lanes (h) and store
#pragma unroll
    for (int t = 0; t < 8; t++) {
#pragma unroll
        for (int j = 0; j < 4; j++) {
            float s = acc[t][j];
#pragma unroll
            for (int off = 16; off > 0; off >>= 1)
                s += __shfl_xor_sync(0xffffffffu, s, off);
            if (lane == 0)
                g_mid[(size_t)(g0 + 8 * tg + t) * R_DIM + 4 * rg + j] = s;
        }
    }
}

// ---------------------------------------------------------------------------
// Kernel 2: out[g][h] = result[g][h] + sum_r mid[g][r] * Bt[e][r][h]
// R11-exact champion. TB2=16, two batches of 8 tokens.
// ---------------------------------------------------------------------------
__global__ __launch_bounds__(NTHREADS)
void lora_out_kernel(const float* __restrict__ result,
                     float* __restrict__ out)
{
    const int tid = threadIdx.x;
    const int g0  = blockIdx.x * TB2;
    const int e   = g0 >> 12;
    const int h4  = (blockIdx.y * NTHREADS + tid) * 4;
    const float* btBase = g_bt + (size_t)e * (R_DIM * H_DIM);

    __shared__ float smid[TB2 * R_DIM];
    smid[tid] = g_mid[(size_t)g0 * R_DIM + tid];
    __syncthreads();

    float4 acc[TB2];
#pragma unroll
    for (int t = 0; t < 8; t++)
        acc[t] = __ldcs((const float4*)(result + (size_t)(g0 + t) * H_DIM + h4));

#pragma unroll
    for (int r = 0; r < R_DIM; r++) {
        const float4 b4 = *(const float4*)(btBase + (size_t)r * H_DIM + h4);
#pragma unroll
        for (int t = 0; t < 8; t++) {
            const float m = smid[t * R_DIM + r];
            acc[t].x += m * b4.x;
            acc[t].y += m * b4.y;
            acc[t].z += m * b4.z;
            acc[t].w += m * b4.w;
        }
    }
#pragma unroll
    for (int t = 0; t < 8; t++)
        __stcs((float4*)(out + (size_t)(g0 + t) * H_DIM + h4), acc[t]);

#pragma unroll
    for (int t = 8; t < TB2; t++)
        acc[t] = __ldcs((const float4*)(result + (size_t)(g0 + t) * H_DIM + h4));

#pragma unroll
    for (int r = 0; r < R_DIM; r++) {
        const float4 b4 = *(const float4*)(btBase + (size_t)r * H_DIM + h4);
#pragma unroll
        for (int t = 8; t < TB2; t++) {
            const float m = smid[t * R_DIM + r];
            acc[t].x += m * b4.x;
            acc[t].y += m * b4.y;
            acc[t].z += m * b4.z;
            acc[t].w += m * b4.w;
        }
    }
#pragma unroll
    for (int t = 8; t < TB2; t++)
        __stcs((float4*)(out + (size_t)(g0 + t) * H_DIM + h4), acc[t]);
}

// ---------------------------------------------------------------------------
// Launch order: mid FIRST (ncu -s5 -c1 profiles lora_mid), then transpose,
// then out. Dependencies respected.
// ---------------------------------------------------------------------------
extern "C" void kernel_launch(void* const* d_in, const int* in_sizes, int n_in,
                              void* d_out, int out_size)
{
    const float* result   = (const float*)d_in[0];
    const float* data     = (const float*)d_in[1];
    const float* dropmask = (const float*)d_in[2];
    const float* lora_a   = (const float*)d_in[3];
    const float* lora_b   = (const float*)d_in[4];
    float* out = (float*)d_out;

    lora_mid_kernel<<<N_TOK / K1_TB, NTHREADS>>>(data, dropmask, lora_a);
    transpose_b_kernel<<<(8 * R_DIM * H_DIM) / NTHREADS, NTHREADS>>>(lora_b);

    dim3 grid2(N_TOK / TB2, H_DIM / (4 * NTHREADS));
    lora_out_kernel<<<grid2, NTHREADS>>>(result, out);
}